// round 3
// baseline (speedup 1.0000x reference)
#include <cuda_runtime.h>
#include <cstdint>

// Problem constants
#define M_TOK   32768          // B*S = 4*8192
#define IN_DIM  100
#define H_DIM   256
#define D_DIM   128
#define N_ATT   10
#define GRAV    0.001f
#define STEPSZ  0.01f
#define N_ITERS 50
#define EPS_F   1e-8f

#define OUT_FIELD_ELEMS (M_TOK * D_DIM)     // 4194304
#define OUT_REC_ELEMS   (M_TOK * IN_DIM)    // 3276800

// Scratch (device globals — allocation-free rule)
__device__ float g_H[M_TOK * H_DIM];     // hidden (reused encoder+decoder)
__device__ float g_EMB[M_TOK * D_DIM];   // encoder output / p0
__device__ float g_Gram[N_ATT * N_ATT];  // attractor Gram matrix
__device__ float g_change;               // accumulated |dp|^2 at last iter

// ---------------------------------------------------------------------------
// Tiled fp32 GEMM: C[M,N] = act(A[M,K] @ W[K,N] + bias)
// BM=128, BN=64, BK=16, 256 threads, 8x4 micro-tile per thread.
// ---------------------------------------------------------------------------
template<bool RELU>
__global__ __launch_bounds__(256)
void gemm_kernel(const float* __restrict__ A, const float* __restrict__ Wt,
                 const float* __restrict__ bias, float* __restrict__ C,
                 int M, int N, int K)
{
    __shared__ float As[16][128];
    __shared__ float Bs[16][64];

    const int tid  = threadIdx.x;
    const int bm   = blockIdx.x * 128;
    const int bn   = blockIdx.y * 64;
    const int trow = tid >> 4;     // 0..15
    const int tcol = tid & 15;     // 0..15
    const int m0   = trow * 8;
    const int n0   = tcol * 4;

    float acc[8][4];
    #pragma unroll
    for (int i = 0; i < 8; i++)
        #pragma unroll
        for (int j = 0; j < 4; j++) acc[i][j] = 0.f;

    for (int k0 = 0; k0 < K; k0 += 16) {
        // load A tile 128x16 (8 elems/thread), coalesced along K
        #pragma unroll
        for (int i = 0; i < 8; i++) {
            int idx = tid + i * 256;
            int r = idx >> 4, c = idx & 15;
            float v = 0.f;
            if (k0 + c < K) v = A[(size_t)(bm + r) * K + k0 + c];
            As[c][r] = v;
        }
        // load W tile 16x64 (4 elems/thread), coalesced along N
        #pragma unroll
        for (int i = 0; i < 4; i++) {
            int idx = tid + i * 256;
            int r = idx >> 6, c = idx & 63;
            float v = 0.f;
            if ((k0 + r < K) && (bn + c < N)) v = Wt[(size_t)(k0 + r) * N + bn + c];
            Bs[r][c] = v;
        }
        __syncthreads();

        #pragma unroll
        for (int kk = 0; kk < 16; kk++) {
            float a[8], b[4];
            #pragma unroll
            for (int i = 0; i < 8; i++) a[i] = As[kk][m0 + i];
            #pragma unroll
            for (int j = 0; j < 4; j++) b[j] = Bs[kk][n0 + j];
            #pragma unroll
            for (int i = 0; i < 8; i++)
                #pragma unroll
                for (int j = 0; j < 4; j++)
                    acc[i][j] += a[i] * b[j];
        }
        __syncthreads();
    }

    #pragma unroll
    for (int i = 0; i < 8; i++) {
        int m = bm + m0 + i;
        #pragma unroll
        for (int j = 0; j < 4; j++) {
            int n = bn + n0 + j;
            if (n < N) {
                float v = acc[i][j] + bias[n];
                if (RELU) v = fmaxf(v, 0.f);
                C[(size_t)m * N + n] = v;
            }
        }
    }
}

// ---------------------------------------------------------------------------
// Precompute 10x10 attractor Gram matrix; also zero the change accumulator.
// ---------------------------------------------------------------------------
__global__ void gram_kernel(const float* __restrict__ attr)
{
    int i = threadIdx.x;
    if (i == 0) g_change = 0.f;
    if (i < N_ATT * N_ATT) {
        int a = i / N_ATT, b = i % N_ATT;
        float s = 0.f;
        for (int d = 0; d < D_DIM; d++)
            s += attr[a * D_DIM + d] * attr[b * D_DIM + d];
        g_Gram[i] = s;
    }
}

// ---------------------------------------------------------------------------
// Attractor dynamics in the 10-dim dual space (49 iters), then one explicit
// fp32 step in D-dim space to reproduce the reference's quantized "change".
// One thread per token.
// ---------------------------------------------------------------------------
__global__ __launch_bounds__(256)
void attractor_kernel(const float* __restrict__ emb,
                      const float* __restrict__ attr,
                      float* __restrict__ out_field)
{
    __shared__ float4 sA[N_ATT][32];     // attractors as float4 over dims
    __shared__ float  sG[N_ATT * N_ATT]; // Gram
    __shared__ float  red[256];

    const int tid = threadIdx.x;
    for (int i = tid; i < N_ATT * 32; i += blockDim.x) {
        int a = i / 32, c = i % 32;
        sA[a][c] = reinterpret_cast<const float4*>(attr)[a * 32 + c];
    }
    for (int i = tid; i < N_ATT * N_ATT; i += blockDim.x) sG[i] = g_Gram[i];
    __syncthreads();

    const int tok = blockIdx.x * blockDim.x + tid;
    const float4* e4 = reinterpret_cast<const float4*>(emb + (size_t)tok * D_DIM);

    // Init dual state: g_a = A_a . p0, q = |p0|^2
    float g[N_ATT];
    #pragma unroll
    for (int a = 0; a < N_ATT; a++) g[a] = 0.f;
    float q = 0.f;
    #pragma unroll 4
    for (int c = 0; c < 32; c++) {
        float4 e = e4[c];
        q += e.x * e.x + e.y * e.y + e.z * e.z + e.w * e.w;
        #pragma unroll
        for (int a = 0; a < N_ATT; a++) {
            float4 av = sA[a][c];
            g[a] += e.x * av.x + e.y * av.y + e.z * av.z + e.w * av.w;
        }
    }

    float W[N_ATT];
    #pragma unroll
    for (int a = 0; a < N_ATT; a++) W[a] = 0.f;
    float Atot = 1.f;
    const float SG = STEPSZ * GRAV;   // 1e-5

    // 49 iterations in dual space
    #pragma unroll 1
    for (int t = 0; t < N_ITERS - 1; t++) {
        float s[N_ATT], S = 0.f;
        #pragma unroll
        for (int a = 0; a < N_ATT; a++) {
            float d2   = sG[a * N_ATT + a] - 2.f * g[a] + q;
            float dist = sqrtf(d2) + EPS_F;
            float ss   = __fdividef(SG, dist * dist * dist);
            s[a] = ss;
            S += ss;
        }
        float alpha = 1.f - S;
        float v[N_ATT], sv = 0.f, sg = 0.f;
        #pragma unroll
        for (int a = 0; a < N_ATT; a++) {
            float va = 0.f;
            #pragma unroll
            for (int b = 0; b < N_ATT; b++) va += s[b] * sG[a * N_ATT + b];
            v[a] = va;
            sv += s[a] * va;
            sg += s[a] * g[a];
        }
        q = alpha * alpha * q + 2.f * alpha * sg + sv;
        #pragma unroll
        for (int a = 0; a < N_ATT; a++) {
            g[a] = alpha * g[a] + v[a];
            W[a] = alpha * W[a] + s[a];
        }
        Atot *= alpha;
    }

    // Step-50 coefficients from the dual state at t=49
    float s[N_ATT], S = 0.f;
    #pragma unroll
    for (int a = 0; a < N_ATT; a++) {
        float d2   = sG[a * N_ATT + a] - 2.f * g[a] + q;
        float dist = sqrtf(d2) + EPS_F;
        float ss   = __fdividef(SG, dist * dist * dist);
        s[a] = ss;
        S += ss;
    }

    // Reconstruct p49 per element, take one explicit fp32 step, measure the
    // quantized change exactly like the reference (new_pos - pos in fp32).
    float chg2 = 0.f;
    float4* o4 = reinterpret_cast<float4*>(out_field + (size_t)tok * D_DIM);
    #pragma unroll 4
    for (int c = 0; c < 32; c++) {
        float4 e = e4[c];
        float4 p;   // p49
        p.x = Atot * e.x; p.y = Atot * e.y; p.z = Atot * e.z; p.w = Atot * e.w;
        float4 f;   // step delta: sum_a s_a*A_a[e] - S*p[e]
        f.x = -S * p.x; f.y = -S * p.y; f.z = -S * p.z; f.w = -S * p.w;
        #pragma unroll
        for (int a = 0; a < N_ATT; a++) {
            float4 av = sA[a][c];
            p.x += W[a] * av.x; p.y += W[a] * av.y;
            p.z += W[a] * av.z; p.w += W[a] * av.w;
            f.x += s[a] * av.x; f.y += s[a] * av.y;
            f.z += s[a] * av.z; f.w += s[a] * av.w;
        }
        // f currently = sum s_a A[e] - S*p49_partial... recompute with final p:
        // NOTE: f was accumulated with -S*p BEFORE the W-updates of p; fix:
        // delta = (sum_a s_a*A[e]) - S*p  => adjust with the W part of p.
        // Instead compute delta cleanly:
        float sAx = 0.f, sAy = 0.f, sAz = 0.f, sAw = 0.f;
        #pragma unroll
        for (int a = 0; a < N_ATT; a++) {
            float4 av = sA[a][c];
            sAx += s[a] * av.x; sAy += s[a] * av.y;
            sAz += s[a] * av.z; sAw += s[a] * av.w;
        }
        float4 np;
        np.x = p.x + (sAx - S * p.x);
        np.y = p.y + (sAy - S * p.y);
        np.z = p.z + (sAz - S * p.z);
        np.w = p.w + (sAw - S * p.w);
        float dx = np.x - p.x, dy = np.y - p.y, dz = np.z - p.z, dw = np.w - p.w;
        chg2 += dx * dx + dy * dy + dz * dz + dw * dw;
        o4[c] = np;
    }

    // Block-reduce change^2, one atomic per block
    red[tid] = chg2;
    __syncthreads();
    for (int sft = 128; sft > 0; sft >>= 1) {
        if (tid < sft) red[tid] += red[tid + sft];
        __syncthreads();
    }
    if (tid == 0) atomicAdd(&g_change, red[0]);
}

__global__ void finish_kernel(float* __restrict__ out)
{
    out[0] = sqrtf(g_change);
}

// ---------------------------------------------------------------------------
extern "C" void kernel_launch(void* const* d_in, const int* in_sizes, int n_in,
                              void* d_out, int out_size)
{
    const float* text   = (const float*)d_in[0];
    const float* enc_w1 = (const float*)d_in[1];
    const float* enc_b1 = (const float*)d_in[2];
    const float* enc_w2 = (const float*)d_in[3];
    const float* enc_b2 = (const float*)d_in[4];
    const float* attr   = (const float*)d_in[5];
    const float* dec_w1 = (const float*)d_in[6];
    const float* dec_b1 = (const float*)d_in[7];
    const float* dec_w2 = (const float*)d_in[8];
    const float* dec_b2 = (const float*)d_in[9];

    float* out       = (float*)d_out;
    float* out_field = out;                           // [32768,128]
    float* out_rec   = out + OUT_FIELD_ELEMS;         // [32768,100]
    float* out_chg   = out + OUT_FIELD_ELEMS + OUT_REC_ELEMS;

    float* H   = nullptr; cudaGetSymbolAddress((void**)&H,   g_H);
    float* EMB = nullptr; cudaGetSymbolAddress((void**)&EMB, g_EMB);

    dim3 blk(256);

    // Encoder layer 1: [M,100] @ [100,256] + b, ReLU
    gemm_kernel<true><<<dim3(M_TOK / 128, H_DIM / 64), blk>>>(
        text, enc_w1, enc_b1, H, M_TOK, H_DIM, IN_DIM);
    // Encoder layer 2: [M,256] @ [256,128] + b
    gemm_kernel<false><<<dim3(M_TOK / 128, D_DIM / 64), blk>>>(
        H, enc_w2, enc_b2, EMB, M_TOK, D_DIM, H_DIM);

    // Gram precompute + change accumulator reset
    gram_kernel<<<1, 128>>>(attr);

    // Attractor dynamics -> writes attractor_field directly to d_out
    attractor_kernel<<<M_TOK / 256, 256>>>(EMB, attr, out_field);

    // Decoder layer 1: [M,128] @ [128,256] + b, ReLU (reads field from d_out)
    gemm_kernel<true><<<dim3(M_TOK / 128, H_DIM / 64), blk>>>(
        out_field, dec_w1, dec_b1, H, M_TOK, H_DIM, D_DIM);
    // Decoder layer 2: [M,256] @ [256,100] + b
    gemm_kernel<false><<<dim3(M_TOK / 128, (IN_DIM + 63) / 64), blk>>>(
        H, dec_w2, dec_b2, out_rec, M_TOK, IN_DIM, H_DIM);

    // final_change scalar
    finish_kernel<<<1, 1>>>(out_chg);
}

// round 4
// speedup vs baseline: 1.5589x; 1.5589x over previous
#include <cuda_runtime.h>
#include <cstdint>

// Problem constants
#define M_TOK   32768          // B*S = 4*8192
#define IN_DIM  100
#define H_DIM   256
#define D_DIM   128
#define N_ATT   10
#define GRAV    0.001f
#define STEPSZ  0.01f
#define N_ITERS 50
#define EPS_F   1e-8f

#define OUT_FIELD_ELEMS (M_TOK * D_DIM)     // 4194304
#define OUT_REC_ELEMS   (M_TOK * IN_DIM)    // 3276800

// Scratch (device globals — allocation-free rule)
__device__ float g_H[M_TOK * H_DIM];     // hidden (reused encoder+decoder)
__device__ float g_EMB[M_TOK * D_DIM];   // encoder output / p0
__device__ float g_Gram[N_ATT * N_ATT];  // attractor Gram matrix
__device__ float g_change;               // accumulated |dp|^2 at last iter

// Packed fp32x2 helpers (Blackwell FFMA2 path)
#define FMA_F32X2(acc, a, b) \
    asm("fma.rn.f32x2 %0, %1, %2, %0;" : "+l"(acc) : "l"(a), "l"(b))
#define DUP_F32X2(out, fbits) \
    asm("mov.b64 %0, {%1, %1};" : "=l"(out) : "r"(fbits))
#define UNPACK_F32X2(lo, hi, in) \
    asm("mov.b64 {%0, %1}, %2;" : "=r"(lo), "=r"(hi) : "l"(in))

// ---------------------------------------------------------------------------
// Tiled fp32 GEMM with packed f32x2 FMA: C[M,N] = act(A[M,K] @ W[K,N] + bias)
// BM=128, BN=64, BK=16, 256 threads. Thread tile 8(M) x 4(N), accumulators
// packed in PAIRS ALONG M so the a-operand pairs load directly as double2
// from shared memory (bit-packed fp32x2, no packing movs needed).
// ---------------------------------------------------------------------------
template<bool RELU>
__global__ __launch_bounds__(256)
void gemm_kernel(const float* __restrict__ A, const float* __restrict__ Wt,
                 const float* __restrict__ bias, float* __restrict__ C,
                 int M, int N, int K)
{
    __shared__ float As[16][132];   // transposed A tile, padded (132*4 % 16 == 0)
    __shared__ float Bs[16][64];

    const int tid  = threadIdx.x;
    const int bm   = blockIdx.x * 128;
    const int bn   = blockIdx.y * 64;
    const int trow = tid >> 4;     // 0..15
    const int tcol = tid & 15;     // 0..15
    const int m0   = trow * 8;
    const int n0   = tcol * 4;

    // acc[mp][j] packs rows (m0+2mp, m0+2mp+1), column n0+j
    unsigned long long acc[4][4];
    #pragma unroll
    for (int i = 0; i < 4; i++)
        #pragma unroll
        for (int j = 0; j < 4; j++) acc[i][j] = 0ull;

    for (int k0 = 0; k0 < K; k0 += 16) {
        // load A tile 128x16 -> transposed As[c][r] (8 elems/thread)
        #pragma unroll
        for (int i = 0; i < 8; i++) {
            int idx = tid + i * 256;
            int r = idx >> 4, c = idx & 15;
            float v = 0.f;
            if (k0 + c < K) v = A[(size_t)(bm + r) * K + k0 + c];
            As[c][r] = v;
        }
        // load W tile 16x64 (4 elems/thread), coalesced along N
        #pragma unroll
        for (int i = 0; i < 4; i++) {
            int idx = tid + i * 256;
            int r = idx >> 6, c = idx & 63;
            float v = 0.f;
            if ((k0 + r < K) && (bn + c < N)) v = Wt[(size_t)(k0 + r) * N + bn + c];
            Bs[r][c] = v;
        }
        __syncthreads();

        #pragma unroll
        for (int kk = 0; kk < 16; kk++) {
            // a pairs: 8 consecutive M values = 4 packed f32x2, loaded as double2
            double2 alo = *reinterpret_cast<const double2*>(&As[kk][m0]);
            double2 ahi = *reinterpret_cast<const double2*>(&As[kk][m0 + 4]);
            unsigned long long ap[4];
            ap[0] = __double_as_longlong(alo.x);
            ap[1] = __double_as_longlong(alo.y);
            ap[2] = __double_as_longlong(ahi.x);
            ap[3] = __double_as_longlong(ahi.y);
            // b values duplicated into both lanes
            float4 bv = *reinterpret_cast<const float4*>(&Bs[kk][n0]);
            unsigned long long bd[4];
            DUP_F32X2(bd[0], __float_as_uint(bv.x));
            DUP_F32X2(bd[1], __float_as_uint(bv.y));
            DUP_F32X2(bd[2], __float_as_uint(bv.z));
            DUP_F32X2(bd[3], __float_as_uint(bv.w));
            #pragma unroll
            for (int mp = 0; mp < 4; mp++)
                #pragma unroll
                for (int j = 0; j < 4; j++)
                    FMA_F32X2(acc[mp][j], ap[mp], bd[j]);
        }
        __syncthreads();
    }

    // Epilogue: unpack, bias, relu, store
    float b4[4];
    #pragma unroll
    for (int j = 0; j < 4; j++) {
        int n = bn + n0 + j;
        b4[j] = (n < N) ? bias[n] : 0.f;
    }
    const bool full = (bn + 64 <= N);
    #pragma unroll
    for (int mp = 0; mp < 4; mp++) {
        float v0[4], v1[4];
        #pragma unroll
        for (int j = 0; j < 4; j++) {
            unsigned lo, hi;
            UNPACK_F32X2(lo, hi, acc[mp][j]);
            float a0 = __uint_as_float(lo) + b4[j];
            float a1 = __uint_as_float(hi) + b4[j];
            if (RELU) { a0 = fmaxf(a0, 0.f); a1 = fmaxf(a1, 0.f); }
            v0[j] = a0; v1[j] = a1;
        }
        int mA = bm + m0 + 2 * mp;
        if (full) {
            *reinterpret_cast<float4*>(&C[(size_t)mA * N + bn + n0]) =
                make_float4(v0[0], v0[1], v0[2], v0[3]);
            *reinterpret_cast<float4*>(&C[(size_t)(mA + 1) * N + bn + n0]) =
                make_float4(v1[0], v1[1], v1[2], v1[3]);
        } else {
            #pragma unroll
            for (int j = 0; j < 4; j++) {
                int n = bn + n0 + j;
                if (n < N) {
                    C[(size_t)mA * N + n]       = v0[j];
                    C[(size_t)(mA + 1) * N + n] = v1[j];
                }
            }
        }
    }
}

// ---------------------------------------------------------------------------
// Precompute 10x10 attractor Gram matrix; also zero the change accumulator.
// ---------------------------------------------------------------------------
__global__ void gram_kernel(const float* __restrict__ attr)
{
    int i = threadIdx.x;
    if (i == 0) g_change = 0.f;
    if (i < N_ATT * N_ATT) {
        int a = i / N_ATT, b = i % N_ATT;
        float s = 0.f;
        for (int d = 0; d < D_DIM; d++)
            s += attr[a * D_DIM + d] * attr[b * D_DIM + d];
        g_Gram[i] = s;
    }
}

// ---------------------------------------------------------------------------
// Attractor dynamics in the 10-dim dual space (49 iters), then one explicit
// fp32 step in D-dim space to reproduce the reference's quantized "change".
// One thread per token. 128 threads/block -> 256 blocks (covers all SMs).
// ---------------------------------------------------------------------------
__global__ __launch_bounds__(128)
void attractor_kernel(const float* __restrict__ emb,
                      const float* __restrict__ attr,
                      float* __restrict__ out_field)
{
    __shared__ float4 sA[N_ATT][32];     // attractors as float4 over dims
    __shared__ float  sG[N_ATT * N_ATT]; // Gram
    __shared__ float  red[4];            // per-warp partials

    const int tid = threadIdx.x;
    for (int i = tid; i < N_ATT * 32; i += blockDim.x) {
        int a = i / 32, c = i % 32;
        sA[a][c] = reinterpret_cast<const float4*>(attr)[a * 32 + c];
    }
    for (int i = tid; i < N_ATT * N_ATT; i += blockDim.x) sG[i] = g_Gram[i];
    __syncthreads();

    const int tok = blockIdx.x * blockDim.x + tid;
    const float4* e4 = reinterpret_cast<const float4*>(emb + (size_t)tok * D_DIM);

    // Init dual state: g_a = A_a . p0, q = |p0|^2
    float g[N_ATT];
    #pragma unroll
    for (int a = 0; a < N_ATT; a++) g[a] = 0.f;
    float q = 0.f;
    #pragma unroll 4
    for (int c = 0; c < 32; c++) {
        float4 e = e4[c];
        q += e.x * e.x + e.y * e.y + e.z * e.z + e.w * e.w;
        #pragma unroll
        for (int a = 0; a < N_ATT; a++) {
            float4 av = sA[a][c];
            g[a] += e.x * av.x + e.y * av.y + e.z * av.z + e.w * av.w;
        }
    }

    float W[N_ATT];
    #pragma unroll
    for (int a = 0; a < N_ATT; a++) W[a] = 0.f;
    float Atot = 1.f;
    const float SG = STEPSZ * GRAV;   // 1e-5

    // 49 iterations in dual space. s_a = SG / dist^3 via rsqrt (dist O(1-10),
    // so the reference's +EPS after sqrt is numerically irrelevant).
    #pragma unroll 1
    for (int t = 0; t < N_ITERS - 1; t++) {
        float s[N_ATT], S = 0.f;
        #pragma unroll
        for (int a = 0; a < N_ATT; a++) {
            float d2 = sG[a * N_ATT + a] - 2.f * g[a] + q;
            float r  = rsqrtf(d2);
            float ss = SG * r * r * r;
            s[a] = ss;
            S += ss;
        }
        float alpha = 1.f - S;
        float v[N_ATT], sv = 0.f, sg = 0.f;
        #pragma unroll
        for (int a = 0; a < N_ATT; a++) {
            float va = 0.f;
            #pragma unroll
            for (int b = 0; b < N_ATT; b++) va += s[b] * sG[a * N_ATT + b];
            v[a] = va;
            sv += s[a] * va;
            sg += s[a] * g[a];
        }
        q = alpha * alpha * q + 2.f * alpha * sg + sv;
        #pragma unroll
        for (int a = 0; a < N_ATT; a++) {
            g[a] = alpha * g[a] + v[a];
            W[a] = alpha * W[a] + s[a];
        }
        Atot *= alpha;
    }

    // Step-50 coefficients from the dual state at t=49
    float s[N_ATT], S = 0.f;
    #pragma unroll
    for (int a = 0; a < N_ATT; a++) {
        float d2 = sG[a * N_ATT + a] - 2.f * g[a] + q;
        float r  = rsqrtf(d2);
        float ss = SG * r * r * r;
        s[a] = ss;
        S += ss;
    }

    // Reconstruct p49 per element, take one explicit fp32 step, and measure
    // the quantized change exactly like the reference (new_pos - pos in fp32).
    float chg2 = 0.f;
    float4* o4 = reinterpret_cast<float4*>(out_field + (size_t)tok * D_DIM);
    #pragma unroll 4
    for (int c = 0; c < 32; c++) {
        float4 e = e4[c];
        float px = Atot * e.x, py = Atot * e.y, pz = Atot * e.z, pw = Atot * e.w;
        float fx = 0.f, fy = 0.f, fz = 0.f, fw = 0.f;  // sum_a s_a * A_a[e]
        #pragma unroll
        for (int a = 0; a < N_ATT; a++) {
            float4 av = sA[a][c];
            px += W[a] * av.x; py += W[a] * av.y;
            pz += W[a] * av.z; pw += W[a] * av.w;
            fx += s[a] * av.x; fy += s[a] * av.y;
            fz += s[a] * av.z; fw += s[a] * av.w;
        }
        float nx = px + (fx - S * px);
        float ny = py + (fy - S * py);
        float nz = pz + (fz - S * pz);
        float nw = pw + (fw - S * pw);
        float dx = nx - px, dy = ny - py, dz = nz - pz, dw = nw - pw;
        chg2 += dx * dx + dy * dy + dz * dz + dw * dw;
        o4[c] = make_float4(nx, ny, nz, nw);
    }

    // Warp-shuffle reduce, then one atomic per block
    #pragma unroll
    for (int sft = 16; sft > 0; sft >>= 1)
        chg2 += __shfl_xor_sync(0xFFFFFFFFu, chg2, sft);
    if ((tid & 31) == 0) red[tid >> 5] = chg2;
    __syncthreads();
    if (tid == 0) {
        float t = red[0] + red[1] + red[2] + red[3];
        atomicAdd(&g_change, t);
    }
}

__global__ void finish_kernel(float* __restrict__ out)
{
    out[0] = sqrtf(g_change);
}

// ---------------------------------------------------------------------------
extern "C" void kernel_launch(void* const* d_in, const int* in_sizes, int n_in,
                              void* d_out, int out_size)
{
    const float* text   = (const float*)d_in[0];
    const float* enc_w1 = (const float*)d_in[1];
    const float* enc_b1 = (const float*)d_in[2];
    const float* enc_w2 = (const float*)d_in[3];
    const float* enc_b2 = (const float*)d_in[4];
    const float* attr   = (const float*)d_in[5];
    const float* dec_w1 = (const float*)d_in[6];
    const float* dec_b1 = (const float*)d_in[7];
    const float* dec_w2 = (const float*)d_in[8];
    const float* dec_b2 = (const float*)d_in[9];

    float* out       = (float*)d_out;
    float* out_field = out;                           // [32768,128]
    float* out_rec   = out + OUT_FIELD_ELEMS;         // [32768,100]
    float* out_chg   = out + OUT_FIELD_ELEMS + OUT_REC_ELEMS;

    float* H   = nullptr; cudaGetSymbolAddress((void**)&H,   g_H);
    float* EMB = nullptr; cudaGetSymbolAddress((void**)&EMB, g_EMB);

    dim3 blk(256);

    // Encoder layer 1: [M,100] @ [100,256] + b, ReLU
    gemm_kernel<true><<<dim3(M_TOK / 128, H_DIM / 64), blk>>>(
        text, enc_w1, enc_b1, H, M_TOK, H_DIM, IN_DIM);
    // Encoder layer 2: [M,256] @ [256,128] + b
    gemm_kernel<false><<<dim3(M_TOK / 128, D_DIM / 64), blk>>>(
        H, enc_w2, enc_b2, EMB, M_TOK, D_DIM, H_DIM);

    // Gram precompute + change accumulator reset
    gram_kernel<<<1, 128>>>(attr);

    // Attractor dynamics -> writes attractor_field directly to d_out
    attractor_kernel<<<M_TOK / 128, 128>>>(EMB, attr, out_field);

    // Decoder layer 1: [M,128] @ [128,256] + b, ReLU (reads field from d_out)
    gemm_kernel<true><<<dim3(M_TOK / 128, H_DIM / 64), blk>>>(
        out_field, dec_w1, dec_b1, H, M_TOK, H_DIM, D_DIM);
    // Decoder layer 2: [M,256] @ [256,100] + b
    gemm_kernel<false><<<dim3(M_TOK / 128, (IN_DIM + 63) / 64), blk>>>(
        H, dec_w2, dec_b2, out_rec, M_TOK, IN_DIM, H_DIM);

    // final_change scalar
    finish_kernel<<<1, 1>>>(out_chg);
}

// round 6
// speedup vs baseline: 1.9463x; 1.2485x over previous
#include <cuda_runtime.h>
#include <cuda_bf16.h>
#include <cstdint>

typedef __nv_bfloat16 bf16;

#define M_TOK   32768
#define D_DIM   128
#define N_ATT   10
#define GRAV    0.001f
#define STEPSZ  0.01f
#define N_ITERS 50

#define OUT_FIELD_ELEMS (M_TOK * 128)
#define OUT_REC_ELEMS   (M_TOK * 100)

// ---------------- device scratch (allocation-free rule) --------------------
__device__ bf16  g_Thi[M_TOK * 128], g_Tlo[M_TOK * 128];   // text, K padded 100->128
__device__ bf16  g_Hhi[M_TOK * 256], g_Hlo[M_TOK * 256];   // hidden (enc1/dec1 out)
__device__ bf16  g_Fhi[M_TOK * 128], g_Flo[M_TOK * 128];   // attractor field split
__device__ float g_EMB[M_TOK * 128];                       // enc2 out (fp32)
__device__ bf16  g_W1hi[256 * 128], g_W1lo[256 * 128];     // [N,Kpad] K-major
__device__ bf16  g_W2hi[128 * 256], g_W2lo[128 * 256];
__device__ bf16  g_W3hi[256 * 128], g_W3lo[256 * 128];
__device__ bf16  g_W4hi[128 * 256], g_W4lo[128 * 256];     // N 100->128 padded
__device__ float g_Gram[N_ATT * N_ATT];
__device__ float g_change;

// ---------------- helpers ---------------------------------------------------
__device__ __forceinline__ uint32_t smem_u32(const void* p) {
    uint32_t a;
    asm("{ .reg .u64 t; cvta.to.shared.u64 t, %1; cvt.u32.u64 %0, t; }" : "=r"(a) : "l"(p));
    return a;
}
#define SWZ(off) ((off) ^ (((off) >> 3) & 0x70))

#define LDSM_X4(r0, r1, r2, r3, addr) \
    asm volatile("ldmatrix.sync.aligned.m8n8.x4.shared.b16 {%0,%1,%2,%3}, [%4];" \
        : "=r"(r0), "=r"(r1), "=r"(r2), "=r"(r3) : "r"(addr))

#define MMA16816(d, a0, a1, a2, a3, b0, b1) \
    asm volatile("mma.sync.aligned.m16n8k16.row.col.f32.bf16.bf16.f32 " \
        "{%0,%1,%2,%3}, {%4,%5,%6,%7}, {%8,%9}, {%0,%1,%2,%3};" \
        : "+f"((d)[0]), "+f"((d)[1]), "+f"((d)[2]), "+f"((d)[3]) \
        : "r"(a0), "r"(a1), "r"(a2), "r"(a3), "r"(b0), "r"(b1))

__device__ __forceinline__ void split2(float v, bf16& hi, bf16& lo) {
    hi = __float2bfloat16(v);
    lo = __float2bfloat16(v - __bfloat162float(hi));
}

// ---------------------------------------------------------------------------
// bf16x3-split tensor-core GEMM via warp-level mma.sync (arch-agnostic PTX).
// CTA: 256 threads = 8 warps in 4(M) x 2(N) grid; warp tile 32x32;
// CTA tile 128(M) x 64(N). A: [M, lda] bf16 hi/lo K-major; B: [N, ldb] K-major.
// Augmented K chunks of 64: [hi*hi | hi*lo | lo*hi], fp32 accumulation.
// Smem: 128B rows, SW128 swizzle (conflict-free ldmatrix column reads).
// ---------------------------------------------------------------------------
template<bool RELU, bool SPLIT>
__global__ __launch_bounds__(256)
void mma_gemm(const bf16* __restrict__ Ahi, const bf16* __restrict__ Alo, int lda,
              const bf16* __restrict__ Bhi, const bf16* __restrict__ Blo, int ldb,
              const float* __restrict__ bias,
              float* __restrict__ Cf, bf16* __restrict__ Chi, bf16* __restrict__ Clo,
              int ldc, int N_out, int nc)
{
    __shared__ alignas(1024) char smem[16384 + 8192];
    const uint32_t sA = smem_u32(smem);
    const uint32_t sB = sA + 16384;

    const int tid = threadIdx.x;
    const int wid = tid >> 5, lid = tid & 31;
    const int bm = blockIdx.x * 128, bn = blockIdx.y * 64;
    const int warpM = wid >> 1, warpN = wid & 1;
    const int m_base = warpM * 32, n_base = warpN * 32;
    const int phase = lid >> 3, r_in = lid & 7;

    float acc[2][4][4];
    #pragma unroll
    for (int mt = 0; mt < 2; mt++)
        #pragma unroll
        for (int nt = 0; nt < 4; nt++)
            #pragma unroll
            for (int e = 0; e < 4; e++) acc[mt][nt][e] = 0.f;

    const int nch = 3 * nc;

    // gmem->reg prefetch state
    uint4 aReg[4], bReg[2];
    const int lr = tid >> 3, lc = tid & 7;  // A: row lr + i*32, 16B col lc

    // prefetch chunk 0
    {
        const bf16* Ag = Ahi + (size_t)bm * lda;          // ka = 0, hi*hi
        const bf16* Bg = Bhi + (size_t)bn * ldb;
        #pragma unroll
        for (int i = 0; i < 4; i++)
            aReg[i] = *reinterpret_cast<const uint4*>(Ag + (size_t)(lr + i * 32) * lda + lc * 8);
        #pragma unroll
        for (int i = 0; i < 2; i++)
            bReg[i] = *reinterpret_cast<const uint4*>(Bg + (size_t)(lr + i * 32) * ldb + lc * 8);
    }

    for (int c = 0; c < nch; c++) {
        // store prefetched chunk to smem (swizzled)
        #pragma unroll
        for (int i = 0; i < 4; i++)
            *reinterpret_cast<uint4*>(smem + SWZ((lr + i * 32) * 128 + lc * 16)) = aReg[i];
        #pragma unroll
        for (int i = 0; i < 2; i++)
            *reinterpret_cast<uint4*>(smem + 16384 + SWZ((lr + i * 32) * 128 + lc * 16)) = bReg[i];
        __syncthreads();

        // prefetch next chunk while computing
        if (c + 1 < nch) {
            int cn = c + 1;
            const bf16 *Ab, *Bb; int ka;
            if (cn < nc)          { Ab = Ahi; Bb = Bhi; ka = cn; }
            else if (cn < 2 * nc) { Ab = Ahi; Bb = Blo; ka = cn - nc; }
            else                  { Ab = Alo; Bb = Bhi; ka = cn - 2 * nc; }
            const bf16* Ag = Ab + (size_t)bm * lda + ka * 64;
            const bf16* Bg = Bb + (size_t)bn * ldb + ka * 64;
            #pragma unroll
            for (int i = 0; i < 4; i++)
                aReg[i] = *reinterpret_cast<const uint4*>(Ag + (size_t)(lr + i * 32) * lda + lc * 8);
            #pragma unroll
            for (int i = 0; i < 2; i++)
                bReg[i] = *reinterpret_cast<const uint4*>(Bg + (size_t)(lr + i * 32) * ldb + lc * 8);
        }

        // compute on this chunk: 4 k16 steps
        #pragma unroll
        for (int k16 = 0; k16 < 4; k16++) {
            const int kb = k16 * 32;
            uint32_t af[2][4], bfr[2][4];
            #pragma unroll
            for (int mt = 0; mt < 2; mt++) {
                int row = m_base + mt * 16 + ((phase & 1) << 3) + r_in;
                int col = kb + ((phase >> 1) << 4);
                LDSM_X4(af[mt][0], af[mt][1], af[mt][2], af[mt][3],
                        sA + SWZ(row * 128 + col));
            }
            #pragma unroll
            for (int ng = 0; ng < 2; ng++) {
                int row = n_base + ng * 16 + ((phase >> 1) << 3) + r_in;
                int col = kb + ((phase & 1) << 4);
                LDSM_X4(bfr[ng][0], bfr[ng][1], bfr[ng][2], bfr[ng][3],
                        sB + SWZ(row * 128 + col));
            }
            #pragma unroll
            for (int mt = 0; mt < 2; mt++)
                #pragma unroll
                for (int ng = 0; ng < 2; ng++) {
                    MMA16816(acc[mt][ng * 2 + 0],
                             af[mt][0], af[mt][1], af[mt][2], af[mt][3],
                             bfr[ng][0], bfr[ng][1]);
                    MMA16816(acc[mt][ng * 2 + 1],
                             af[mt][0], af[mt][1], af[mt][2], af[mt][3],
                             bfr[ng][2], bfr[ng][3]);
                }
        }
        __syncthreads();
    }

    // Epilogue: d0,d1 -> (row g, cols t2,t2+1); d2,d3 -> (row g+8)
    const int g = lid >> 2, t2 = (lid & 3) * 2;
    #pragma unroll
    for (int mt = 0; mt < 2; mt++) {
        const int m0r = bm + m_base + mt * 16 + g;
        #pragma unroll
        for (int nt = 0; nt < 4; nt++) {
            const int n = bn + n_base + nt * 8 + t2;
            float b0v = (n < N_out)     ? bias[n]     : 0.f;
            float b1v = (n + 1 < N_out) ? bias[n + 1] : 0.f;
            float v0 = acc[mt][nt][0] + b0v, v1 = acc[mt][nt][1] + b1v;
            float v2 = acc[mt][nt][2] + b0v, v3 = acc[mt][nt][3] + b1v;
            if (RELU) {
                v0 = fmaxf(v0, 0.f); v1 = fmaxf(v1, 0.f);
                v2 = fmaxf(v2, 0.f); v3 = fmaxf(v3, 0.f);
            }
            if (SPLIT) {
                bf16 h0, l0, h1, l1;
                split2(v0, h0, l0); split2(v1, h1, l1);
                __nv_bfloat162 ph; ph.x = h0; ph.y = h1;
                __nv_bfloat162 pl; pl.x = l0; pl.y = l1;
                *reinterpret_cast<__nv_bfloat162*>(Chi + (size_t)m0r * ldc + n) = ph;
                *reinterpret_cast<__nv_bfloat162*>(Clo + (size_t)m0r * ldc + n) = pl;
                split2(v2, h0, l0); split2(v3, h1, l1);
                ph.x = h0; ph.y = h1; pl.x = l0; pl.y = l1;
                *reinterpret_cast<__nv_bfloat162*>(Chi + (size_t)(m0r + 8) * ldc + n) = ph;
                *reinterpret_cast<__nv_bfloat162*>(Clo + (size_t)(m0r + 8) * ldc + n) = pl;
            } else if (n < N_out) {
                *reinterpret_cast<float2*>(Cf + (size_t)m0r * ldc + n)       = make_float2(v0, v1);
                *reinterpret_cast<float2*>(Cf + (size_t)(m0r + 8) * ldc + n) = make_float2(v2, v3);
            }
        }
    }
}

// ---------------------------------------------------------------------------
// Conversion kernels
// ---------------------------------------------------------------------------
__global__ void text_conv(const float* __restrict__ text)
{
    int idx = blockIdx.x * 256 + threadIdx.x;   // M_TOK*128
    int m = idx >> 7, k = idx & 127;
    float v = (k < 100) ? text[(size_t)m * 100 + k] : 0.f;
    bf16 h, l; split2(v, h, l);
    g_Thi[idx] = h; g_Tlo[idx] = l;
}

__global__ void wconv(const float* __restrict__ W, bf16* __restrict__ Bhi,
                      bf16* __restrict__ Blo, int K, int N, int K_pad, int total)
{
    int idx = blockIdx.x * 256 + threadIdx.x;
    if (idx >= total) return;
    int n = idx / K_pad, k = idx % K_pad;
    float v = (n < N && k < K) ? W[(size_t)k * N + n] : 0.f;
    bf16 h, l; split2(v, h, l);
    Bhi[idx] = h; Blo[idx] = l;
}

// ---------------------------------------------------------------------------
__global__ void gram_kernel(const float* __restrict__ attr)
{
    int i = threadIdx.x;
    if (i == 0) g_change = 0.f;
    if (i < N_ATT * N_ATT) {
        int a = i / N_ATT, b = i % N_ATT;
        float s = 0.f;
        for (int d = 0; d < D_DIM; d++)
            s += attr[a * D_DIM + d] * attr[b * D_DIM + d];
        g_Gram[i] = s;
    }
}

// ---------------------------------------------------------------------------
// Attractor dynamics (dual space, 49 iters + explicit quantized 50th step).
// Writes fp32 field to d_out AND bf16 hi/lo split for the next GEMM.
// ---------------------------------------------------------------------------
__global__ __launch_bounds__(128)
void attractor_kernel(const float* __restrict__ emb,
                      const float* __restrict__ attr,
                      float* __restrict__ out_field)
{
    __shared__ float4 sA[N_ATT][32];
    __shared__ float  sG[N_ATT * N_ATT];
    __shared__ float  red[4];

    const int tid = threadIdx.x;
    for (int i = tid; i < N_ATT * 32; i += blockDim.x) {
        int a = i / 32, c = i % 32;
        sA[a][c] = reinterpret_cast<const float4*>(attr)[a * 32 + c];
    }
    for (int i = tid; i < N_ATT * N_ATT; i += blockDim.x) sG[i] = g_Gram[i];
    __syncthreads();

    const int tok = blockIdx.x * blockDim.x + tid;
    const float4* e4 = reinterpret_cast<const float4*>(emb + (size_t)tok * D_DIM);

    float g[N_ATT];
    #pragma unroll
    for (int a = 0; a < N_ATT; a++) g[a] = 0.f;
    float q = 0.f;
    #pragma unroll 4
    for (int c = 0; c < 32; c++) {
        float4 e = e4[c];
        q += e.x*e.x + e.y*e.y + e.z*e.z + e.w*e.w;
        #pragma unroll
        for (int a = 0; a < N_ATT; a++) {
            float4 av = sA[a][c];
            g[a] += e.x*av.x + e.y*av.y + e.z*av.z + e.w*av.w;
        }
    }

    float W[N_ATT];
    #pragma unroll
    for (int a = 0; a < N_ATT; a++) W[a] = 0.f;
    float Atot = 1.f;
    const float SG = STEPSZ * GRAV;

    #pragma unroll 1
    for (int t = 0; t < N_ITERS - 1; t++) {
        float s[N_ATT], S = 0.f;
        #pragma unroll
        for (int a = 0; a < N_ATT; a++) {
            float d2 = sG[a * N_ATT + a] - 2.f * g[a] + q;
            float r  = rsqrtf(d2);
            float ss = SG * r * r * r;
            s[a] = ss; S += ss;
        }
        float alpha = 1.f - S;
        float v[N_ATT], sv = 0.f, sg = 0.f;
        #pragma unroll
        for (int a = 0; a < N_ATT; a++) {
            float va = 0.f;
            #pragma unroll
            for (int b = 0; b < N_ATT; b++) va += s[b] * sG[a * N_ATT + b];
            v[a] = va; sv += s[a] * va; sg += s[a] * g[a];
        }
        q = alpha * alpha * q + 2.f * alpha * sg + sv;
        #pragma unroll
        for (int a = 0; a < N_ATT; a++) {
            g[a] = alpha * g[a] + v[a];
            W[a] = alpha * W[a] + s[a];
        }
        Atot *= alpha;
    }

    float s[N_ATT], S = 0.f;
    #pragma unroll
    for (int a = 0; a < N_ATT; a++) {
        float d2 = sG[a * N_ATT + a] - 2.f * g[a] + q;
        float r  = rsqrtf(d2);
        float ss = SG * r * r * r;
        s[a] = ss; S += ss;
    }

    float chg2 = 0.f;
    float4* o4 = reinterpret_cast<float4*>(out_field + (size_t)tok * D_DIM);
    bf16* fh = g_Fhi + (size_t)tok * D_DIM;
    bf16* fl = g_Flo + (size_t)tok * D_DIM;
    #pragma unroll 4
    for (int c = 0; c < 32; c++) {
        float4 e = e4[c];
        float px = Atot*e.x, py = Atot*e.y, pz = Atot*e.z, pw = Atot*e.w;
        float fx = 0.f, fy = 0.f, fz = 0.f, fw = 0.f;
        #pragma unroll
        for (int a = 0; a < N_ATT; a++) {
            float4 av = sA[a][c];
            px += W[a]*av.x; py += W[a]*av.y; pz += W[a]*av.z; pw += W[a]*av.w;
            fx += s[a]*av.x; fy += s[a]*av.y; fz += s[a]*av.z; fw += s[a]*av.w;
        }
        float nx = px + (fx - S*px);
        float ny = py + (fy - S*py);
        float nz = pz + (fz - S*pz);
        float nw = pw + (fw - S*pw);
        float dx = nx-px, dy = ny-py, dz = nz-pz, dw = nw-pw;
        chg2 += dx*dx + dy*dy + dz*dz + dw*dw;
        o4[c] = make_float4(nx, ny, nz, nw);

        bf16 h0,l0,h1,l1,h2,l2,h3,l3;
        split2(nx,h0,l0); split2(ny,h1,l1); split2(nz,h2,l2); split2(nw,h3,l3);
        __nv_bfloat162 ph0; ph0.x=h0; ph0.y=h1;
        __nv_bfloat162 ph1; ph1.x=h2; ph1.y=h3;
        __nv_bfloat162 pl0; pl0.x=l0; pl0.y=l1;
        __nv_bfloat162 pl1; pl1.x=l2; pl1.y=l3;
        *reinterpret_cast<__nv_bfloat162*>(fh + c*4)     = ph0;
        *reinterpret_cast<__nv_bfloat162*>(fh + c*4 + 2) = ph1;
        *reinterpret_cast<__nv_bfloat162*>(fl + c*4)     = pl0;
        *reinterpret_cast<__nv_bfloat162*>(fl + c*4 + 2) = pl1;
    }

    #pragma unroll
    for (int sft = 16; sft > 0; sft >>= 1)
        chg2 += __shfl_xor_sync(0xFFFFFFFFu, chg2, sft);
    if ((tid & 31) == 0) red[tid >> 5] = chg2;
    __syncthreads();
    if (tid == 0) atomicAdd(&g_change, red[0] + red[1] + red[2] + red[3]);
}

__global__ void finish_kernel(float* __restrict__ out)
{
    out[0] = sqrtf(g_change);
}

// ---------------------------------------------------------------------------
extern "C" void kernel_launch(void* const* d_in, const int* in_sizes, int n_in,
                              void* d_out, int out_size)
{
    const float* text   = (const float*)d_in[0];
    const float* enc_w1 = (const float*)d_in[1];
    const float* enc_b1 = (const float*)d_in[2];
    const float* enc_w2 = (const float*)d_in[3];
    const float* enc_b2 = (const float*)d_in[4];
    const float* attr   = (const float*)d_in[5];
    const float* dec_w1 = (const float*)d_in[6];
    const float* dec_b1 = (const float*)d_in[7];
    const float* dec_w2 = (const float*)d_in[8];
    const float* dec_b2 = (const float*)d_in[9];

    float* out       = (float*)d_out;
    float* out_field = out;
    float* out_rec   = out + OUT_FIELD_ELEMS;
    float* out_chg   = out + OUT_FIELD_ELEMS + OUT_REC_ELEMS;

    bf16 *Thi, *Tlo, *Hhi, *Hlo, *Fhi, *Flo;
    bf16 *W1hi, *W1lo, *W2hi, *W2lo, *W3hi, *W3lo, *W4hi, *W4lo;
    float* EMB;
    cudaGetSymbolAddress((void**)&Thi,  g_Thi);  cudaGetSymbolAddress((void**)&Tlo,  g_Tlo);
    cudaGetSymbolAddress((void**)&Hhi,  g_Hhi);  cudaGetSymbolAddress((void**)&Hlo,  g_Hlo);
    cudaGetSymbolAddress((void**)&Fhi,  g_Fhi);  cudaGetSymbolAddress((void**)&Flo,  g_Flo);
    cudaGetSymbolAddress((void**)&W1hi, g_W1hi); cudaGetSymbolAddress((void**)&W1lo, g_W1lo);
    cudaGetSymbolAddress((void**)&W2hi, g_W2hi); cudaGetSymbolAddress((void**)&W2lo, g_W2lo);
    cudaGetSymbolAddress((void**)&W3hi, g_W3hi); cudaGetSymbolAddress((void**)&W3lo, g_W3lo);
    cudaGetSymbolAddress((void**)&W4hi, g_W4hi); cudaGetSymbolAddress((void**)&W4lo, g_W4lo);
    cudaGetSymbolAddress((void**)&EMB,  g_EMB);

    // Conversions
    text_conv<<<(M_TOK * 128) / 256, 256>>>(text);
    wconv<<<(256 * 128 + 255) / 256, 256>>>(enc_w1, W1hi, W1lo, 100, 256, 128, 256 * 128);
    wconv<<<(128 * 256 + 255) / 256, 256>>>(enc_w2, W2hi, W2lo, 256, 128, 256, 128 * 256);
    wconv<<<(256 * 128 + 255) / 256, 256>>>(dec_w1, W3hi, W3lo, 128, 256, 128, 256 * 128);
    wconv<<<(128 * 256 + 255) / 256, 256>>>(dec_w2, W4hi, W4lo, 256, 100, 256, 128 * 256);
    gram_kernel<<<1, 128>>>(attr);

    // enc1: [M,100p128] @ W1 -> relu -> H (bf16 split), N=256
    mma_gemm<true, true><<<dim3(M_TOK / 128, 4), 256>>>(
        Thi, Tlo, 128, W1hi, W1lo, 128, enc_b1,
        nullptr, Hhi, Hlo, 256, 256, 2);
    // enc2: [M,256] @ W2 -> EMB fp32, N=128
    mma_gemm<false, false><<<dim3(M_TOK / 128, 2), 256>>>(
        Hhi, Hlo, 256, W2hi, W2lo, 256, enc_b2,
        EMB, nullptr, nullptr, 128, 128, 4);

    attractor_kernel<<<M_TOK / 128, 128>>>(EMB, attr, out_field);

    // dec1: [M,128] @ W3 -> relu -> H (bf16 split), N=256
    mma_gemm<true, true><<<dim3(M_TOK / 128, 4), 256>>>(
        Fhi, Flo, 128, W3hi, W3lo, 128, dec_b1,
        nullptr, Hhi, Hlo, 256, 256, 2);
    // dec2: [M,256] @ W4 -> out_rec fp32, N=100 (ldc=100)
    mma_gemm<false, false><<<dim3(M_TOK / 128, 2), 256>>>(
        Hhi, Hlo, 256, W4hi, W4lo, 256, dec_b2,
        out_rec, nullptr, nullptr, 100, 100, 4);

    finish_kernel<<<1, 1>>>(out_chg);
}

// round 7
// speedup vs baseline: 2.2403x; 1.1510x over previous
#include <cuda_runtime.h>
#include <cuda_bf16.h>
#include <cstdint>

typedef __nv_bfloat16 bf16;

#define M_TOK   32768
#define D_DIM   128
#define N_ATT   10
#define GRAV    0.001f
#define STEPSZ  0.01f
#define N_ITERS 50

#define OUT_FIELD_ELEMS (M_TOK * 128)
#define OUT_REC_ELEMS   (M_TOK * 100)

// ---------------- device scratch (allocation-free rule) --------------------
__device__ bf16  g_Thi[M_TOK * 128], g_Tlo[M_TOK * 128];   // text, K padded 100->128
__device__ bf16  g_Hhi[M_TOK * 256], g_Hlo[M_TOK * 256];   // hidden (enc1/dec1 out)
__device__ bf16  g_Fhi[M_TOK * 128], g_Flo[M_TOK * 128];   // attractor field split
__device__ float g_EMB[M_TOK * 128];                       // enc2 out (fp32)
__device__ bf16  g_W1hi[256 * 128], g_W1lo[256 * 128];     // [N,Kpad] K-major
__device__ bf16  g_W2hi[128 * 256], g_W2lo[128 * 256];
__device__ bf16  g_W3hi[256 * 128], g_W3lo[256 * 128];
__device__ bf16  g_W4hi[128 * 256], g_W4lo[128 * 256];     // N 100->128 padded
__device__ float g_Gram[N_ATT * N_ATT];
__device__ float g_change;

// ---------------- helpers ---------------------------------------------------
__device__ __forceinline__ uint32_t smem_u32(const void* p) {
    uint32_t a;
    asm("{ .reg .u64 t; cvta.to.shared.u64 t, %1; cvt.u32.u64 %0, t; }" : "=r"(a) : "l"(p));
    return a;
}
#define SWZ(off) ((off) ^ (((off) >> 3) & 0x70))

#define CP_ASYNC16(dst, src) \
    asm volatile("cp.async.ca.shared.global [%0], [%1], 16;" :: "r"(dst), "l"(src))
#define CP_COMMIT() asm volatile("cp.async.commit_group;" ::: "memory")
#define CP_WAIT1()  asm volatile("cp.async.wait_group 1;" ::: "memory")
#define CP_WAIT0()  asm volatile("cp.async.wait_group 0;" ::: "memory")

#define LDSM_X4(r0, r1, r2, r3, addr) \
    asm volatile("ldmatrix.sync.aligned.m8n8.x4.shared.b16 {%0,%1,%2,%3}, [%4];" \
        : "=r"(r0), "=r"(r1), "=r"(r2), "=r"(r3) : "r"(addr))

#define MMA16816(d, a0, a1, a2, a3, b0, b1) \
    asm volatile("mma.sync.aligned.m16n8k16.row.col.f32.bf16.bf16.f32 " \
        "{%0,%1,%2,%3}, {%4,%5,%6,%7}, {%8,%9}, {%0,%1,%2,%3};" \
        : "+f"((d)[0]), "+f"((d)[1]), "+f"((d)[2]), "+f"((d)[3]) \
        : "r"(a0), "r"(a1), "r"(a2), "r"(a3), "r"(b0), "r"(b1))

__device__ __forceinline__ void split2(float v, bf16& hi, bf16& lo) {
    hi = __float2bfloat16(v);
    lo = __float2bfloat16(v - __bfloat162float(hi));
}

// ---------------------------------------------------------------------------
// bf16x3-split tensor-core GEMM, cp.async double-buffered.
// CTA: 256 threads = 8 warps (4M x 2N), warp tile 32x32, CTA tile 128x64.
// Augmented K chunks of 64: [hi*hi | hi*lo | lo*hi], fp32 accumulation.
// ---------------------------------------------------------------------------
#define STAGE_BYTES 24576   // 16K A + 8K B, 1024-aligned

template<bool RELU, bool SPLIT>
__global__ __launch_bounds__(256)
void mma_gemm(const bf16* __restrict__ Ahi, const bf16* __restrict__ Alo, int lda,
              const bf16* __restrict__ Bhi, const bf16* __restrict__ Blo, int ldb,
              const float* __restrict__ bias,
              float* __restrict__ Cf, bf16* __restrict__ Chi, bf16* __restrict__ Clo,
              int ldc, int N_out, int nc)
{
    __shared__ alignas(1024) char smem[2 * STAGE_BYTES];
    const uint32_t sbase = smem_u32(smem);

    const int tid = threadIdx.x;
    const int wid = tid >> 5, lid = tid & 31;
    const int bm = blockIdx.x * 128, bn = blockIdx.y * 64;
    const int warpM = wid >> 1, warpN = wid & 1;
    const int m_base = warpM * 32, n_base = warpN * 32;
    const int phase = lid >> 3, r_in = lid & 7;
    const int lr = tid >> 3, lc = tid & 7;

    const int nch = 3 * nc;

    float acc[2][4][4];
    #pragma unroll
    for (int mt = 0; mt < 2; mt++)
        #pragma unroll
        for (int nt = 0; nt < 4; nt++)
            #pragma unroll
            for (int e = 0; e < 4; e++) acc[mt][nt][e] = 0.f;

    // async-load one chunk into a stage
    auto issue = [&](int c, int st) {
        const bf16 *Ab, *Bb; int ka;
        if (c < nc)          { Ab = Ahi; Bb = Bhi; ka = c; }
        else if (c < 2 * nc) { Ab = Ahi; Bb = Blo; ka = c - nc; }
        else                 { Ab = Alo; Bb = Bhi; ka = c - 2 * nc; }
        const bf16* Ag = Ab + (size_t)bm * lda + ka * 64;
        const bf16* Bg = Bb + (size_t)bn * ldb + ka * 64;
        const uint32_t aOff = sbase + st * STAGE_BYTES;
        const uint32_t bOff = aOff + 16384;
        #pragma unroll
        for (int i = 0; i < 4; i++)
            CP_ASYNC16(aOff + SWZ((lr + i * 32) * 128 + lc * 16),
                       Ag + (size_t)(lr + i * 32) * lda + lc * 8);
        #pragma unroll
        for (int i = 0; i < 2; i++)
            CP_ASYNC16(bOff + SWZ((lr + i * 32) * 128 + lc * 16),
                       Bg + (size_t)(lr + i * 32) * ldb + lc * 8);
        CP_COMMIT();
    };

    issue(0, 0);

    for (int c = 0; c < nch; c++) {
        if (c + 1 < nch) { issue(c + 1, (c + 1) & 1); CP_WAIT1(); }
        else             { CP_WAIT0(); }
        __syncthreads();

        const uint32_t sA = sbase + (c & 1) * STAGE_BYTES;
        const uint32_t sB = sA + 16384;
        #pragma unroll
        for (int k16 = 0; k16 < 4; k16++) {
            const int kb = k16 * 32;
            uint32_t af[2][4], bfr[2][4];
            #pragma unroll
            for (int mt = 0; mt < 2; mt++) {
                int row = m_base + mt * 16 + ((phase & 1) << 3) + r_in;
                int col = kb + ((phase >> 1) << 4);
                LDSM_X4(af[mt][0], af[mt][1], af[mt][2], af[mt][3],
                        sA + SWZ(row * 128 + col));
            }
            #pragma unroll
            for (int ng = 0; ng < 2; ng++) {
                int row = n_base + ng * 16 + ((phase >> 1) << 3) + r_in;
                int col = kb + ((phase & 1) << 4);
                LDSM_X4(bfr[ng][0], bfr[ng][1], bfr[ng][2], bfr[ng][3],
                        sB + SWZ(row * 128 + col));
            }
            #pragma unroll
            for (int mt = 0; mt < 2; mt++)
                #pragma unroll
                for (int ng = 0; ng < 2; ng++) {
                    MMA16816(acc[mt][ng * 2 + 0],
                             af[mt][0], af[mt][1], af[mt][2], af[mt][3],
                             bfr[ng][0], bfr[ng][1]);
                    MMA16816(acc[mt][ng * 2 + 1],
                             af[mt][0], af[mt][1], af[mt][2], af[mt][3],
                             bfr[ng][2], bfr[ng][3]);
                }
        }
        __syncthreads();
    }

    // Epilogue
    const int g = lid >> 2, t2 = (lid & 3) * 2;
    #pragma unroll
    for (int mt = 0; mt < 2; mt++) {
        const int m0r = bm + m_base + mt * 16 + g;
        #pragma unroll
        for (int nt = 0; nt < 4; nt++) {
            const int n = bn + n_base + nt * 8 + t2;
            float b0v = (n < N_out)     ? bias[n]     : 0.f;
            float b1v = (n + 1 < N_out) ? bias[n + 1] : 0.f;
            float v0 = acc[mt][nt][0] + b0v, v1 = acc[mt][nt][1] + b1v;
            float v2 = acc[mt][nt][2] + b0v, v3 = acc[mt][nt][3] + b1v;
            if (RELU) {
                v0 = fmaxf(v0, 0.f); v1 = fmaxf(v1, 0.f);
                v2 = fmaxf(v2, 0.f); v3 = fmaxf(v3, 0.f);
            }
            if (SPLIT) {
                bf16 h0, l0, h1, l1;
                split2(v0, h0, l0); split2(v1, h1, l1);
                __nv_bfloat162 ph; ph.x = h0; ph.y = h1;
                __nv_bfloat162 pl; pl.x = l0; pl.y = l1;
                *reinterpret_cast<__nv_bfloat162*>(Chi + (size_t)m0r * ldc + n) = ph;
                *reinterpret_cast<__nv_bfloat162*>(Clo + (size_t)m0r * ldc + n) = pl;
                split2(v2, h0, l0); split2(v3, h1, l1);
                ph.x = h0; ph.y = h1; pl.x = l0; pl.y = l1;
                *reinterpret_cast<__nv_bfloat162*>(Chi + (size_t)(m0r + 8) * ldc + n) = ph;
                *reinterpret_cast<__nv_bfloat162*>(Clo + (size_t)(m0r + 8) * ldc + n) = pl;
            } else if (n < N_out) {
                *reinterpret_cast<float2*>(Cf + (size_t)m0r * ldc + n)       = make_float2(v0, v1);
                *reinterpret_cast<float2*>(Cf + (size_t)(m0r + 8) * ldc + n) = make_float2(v2, v3);
            }
        }
    }
}

// ---------------------------------------------------------------------------
// Fused prep: text split + 4 weight splits + Gram + change reset. One launch.
// blocks [0,16384): text; [16384,16512): W1; [16512,16640): W2;
// [16640,16768): W3; [16768,16896): W4; 16896: gram.
// ---------------------------------------------------------------------------
__device__ __forceinline__ void wsplit_blk(const float* __restrict__ W,
                                           bf16* __restrict__ Bhi, bf16* __restrict__ Blo,
                                           int K, int N, int K_pad, int blk)
{
    int idx = blk * 256 + threadIdx.x;
    int n = idx / K_pad, k = idx % K_pad;
    float v = (n < N && k < K) ? W[(size_t)k * N + n] : 0.f;
    bf16 h, l; split2(v, h, l);
    Bhi[idx] = h; Blo[idx] = l;
}

__global__ void prep_kernel(const float* __restrict__ text,
                            const float* __restrict__ w1, const float* __restrict__ w2,
                            const float* __restrict__ w3, const float* __restrict__ w4,
                            const float* __restrict__ attr)
{
    int b = blockIdx.x;
    if (b < 16384) {
        int idx = b * 256 + threadIdx.x;          // M_TOK*128
        int m = idx >> 7, k = idx & 127;
        float v = (k < 100) ? text[(size_t)m * 100 + k] : 0.f;
        bf16 h, l; split2(v, h, l);
        g_Thi[idx] = h; g_Tlo[idx] = l;
    } else if (b < 16512) {
        wsplit_blk(w1, g_W1hi, g_W1lo, 100, 256, 128, b - 16384);
    } else if (b < 16640) {
        wsplit_blk(w2, g_W2hi, g_W2lo, 256, 128, 256, b - 16512);
    } else if (b < 16768) {
        wsplit_blk(w3, g_W3hi, g_W3lo, 128, 256, 128, b - 16640);
    } else if (b < 16896) {
        wsplit_blk(w4, g_W4hi, g_W4lo, 256, 100, 256, b - 16768);
    } else {
        int i = threadIdx.x;
        if (i == 0) g_change = 0.f;
        if (i < N_ATT * N_ATT) {
            int a = i / N_ATT, bb = i % N_ATT;
            float s = 0.f;
            for (int d = 0; d < D_DIM; d++)
                s += attr[a * D_DIM + d] * attr[bb * D_DIM + d];
            g_Gram[i] = s;
        }
    }
}

// ---------------------------------------------------------------------------
// Attractor dynamics: dual-space 49 iters with Newton-maintained rsqrt
// (1 MUFU per attractor total instead of per iteration), then one explicit
// fp32 step in D-dim to reproduce the reference's quantized "change".
// ---------------------------------------------------------------------------
__global__ __launch_bounds__(128)
void attractor_kernel(const float* __restrict__ emb,
                      const float* __restrict__ attr,
                      float* __restrict__ out_field)
{
    __shared__ float4 sA[N_ATT][32];
    __shared__ alignas(16) float sGp[N_ATT][12];   // padded rows for float4 reads
    __shared__ float  red[4];

    const int tid = threadIdx.x;
    for (int i = tid; i < N_ATT * 32; i += blockDim.x) {
        int a = i / 32, c = i % 32;
        sA[a][c] = reinterpret_cast<const float4*>(attr)[a * 32 + c];
    }
    for (int i = tid; i < N_ATT * 12; i += blockDim.x) {
        int a = i / 12, bb = i % 12;
        sGp[a][bb] = (bb < N_ATT) ? g_Gram[a * N_ATT + bb] : 0.f;
    }
    __syncthreads();

    const int tok = blockIdx.x * blockDim.x + tid;
    const float4* e4 = reinterpret_cast<const float4*>(emb + (size_t)tok * D_DIM);

    float g[N_ATT];
    #pragma unroll
    for (int a = 0; a < N_ATT; a++) g[a] = 0.f;
    float q = 0.f;
    #pragma unroll 4
    for (int c = 0; c < 32; c++) {
        float4 e = e4[c];
        q += e.x*e.x + e.y*e.y + e.z*e.z + e.w*e.w;
        #pragma unroll
        for (int a = 0; a < N_ATT; a++) {
            float4 av = sA[a][c];
            g[a] += e.x*av.x + e.y*av.y + e.z*av.z + e.w*av.w;
        }
    }

    float diag[N_ATT], r[N_ATT];
    #pragma unroll
    for (int a = 0; a < N_ATT; a++) {
        diag[a] = sGp[a][a];
        r[a] = rsqrtf(diag[a] - 2.f * g[a] + q);   // seed; Newton maintains it
    }

    float W[N_ATT];
    #pragma unroll
    for (int a = 0; a < N_ATT; a++) W[a] = 0.f;
    float Atot = 1.f;
    const float SG = STEPSZ * GRAV;

    #pragma unroll 1
    for (int t = 0; t < N_ITERS - 1; t++) {
        float s[N_ATT], S = 0.f;
        #pragma unroll
        for (int a = 0; a < N_ATT; a++) {
            float d2 = diag[a] - 2.f * g[a] + q;
            float rr = r[a];
            rr = rr * (1.5f - 0.5f * d2 * rr * rr);   // Newton: no MUFU
            r[a] = rr;
            float ss = (SG * rr) * (rr * rr);
            s[a] = ss; S += ss;
        }
        float alpha = 1.f - S;
        float v[N_ATT], sv = 0.f, sg = 0.f;
        #pragma unroll
        for (int a = 0; a < N_ATT; a++) {
            const float4 r0 = *reinterpret_cast<const float4*>(&sGp[a][0]);
            const float4 r1 = *reinterpret_cast<const float4*>(&sGp[a][4]);
            const float4 r2 = *reinterpret_cast<const float4*>(&sGp[a][8]);
            float va = r0.x*s[0] + r0.y*s[1] + r0.z*s[2] + r0.w*s[3]
                     + r1.x*s[4] + r1.y*s[5] + r1.z*s[6] + r1.w*s[7]
                     + r2.x*s[8] + r2.y*s[9];
            v[a] = va; sv += s[a] * va; sg += s[a] * g[a];
        }
        q = alpha * alpha * q + 2.f * alpha * sg + sv;
        #pragma unroll
        for (int a = 0; a < N_ATT; a++) {
            g[a] = alpha * g[a] + v[a];
            W[a] = alpha * W[a] + s[a];
        }
        Atot *= alpha;
    }

    // step-50 coefficients
    float s[N_ATT], S = 0.f;
    #pragma unroll
    for (int a = 0; a < N_ATT; a++) {
        float d2 = diag[a] - 2.f * g[a] + q;
        float rr = r[a];
        rr = rr * (1.5f - 0.5f * d2 * rr * rr);
        float ss = (SG * rr) * (rr * rr);
        s[a] = ss; S += ss;
    }

    float chg2 = 0.f;
    float4* o4 = reinterpret_cast<float4*>(out_field + (size_t)tok * D_DIM);
    bf16* fh = g_Fhi + (size_t)tok * D_DIM;
    bf16* fl = g_Flo + (size_t)tok * D_DIM;
    #pragma unroll 4
    for (int c = 0; c < 32; c++) {
        float4 e = e4[c];
        float px = Atot*e.x, py = Atot*e.y, pz = Atot*e.z, pw = Atot*e.w;
        float fx = 0.f, fy = 0.f, fz = 0.f, fw = 0.f;
        #pragma unroll
        for (int a = 0; a < N_ATT; a++) {
            float4 av = sA[a][c];
            px += W[a]*av.x; py += W[a]*av.y; pz += W[a]*av.z; pw += W[a]*av.w;
            fx += s[a]*av.x; fy += s[a]*av.y; fz += s[a]*av.z; fw += s[a]*av.w;
        }
        float nx = px + (fx - S*px);
        float ny = py + (fy - S*py);
        float nz = pz + (fz - S*pz);
        float nw = pw + (fw - S*pw);
        float dx = nx-px, dy = ny-py, dz = nz-pz, dw = nw-pw;
        chg2 += dx*dx + dy*dy + dz*dz + dw*dw;
        o4[c] = make_float4(nx, ny, nz, nw);

        bf16 h0,l0,h1,l1,h2,l2,h3,l3;
        split2(nx,h0,l0); split2(ny,h1,l1); split2(nz,h2,l2); split2(nw,h3,l3);
        __nv_bfloat162 ph0; ph0.x=h0; ph0.y=h1;
        __nv_bfloat162 ph1; ph1.x=h2; ph1.y=h3;
        __nv_bfloat162 pl0; pl0.x=l0; pl0.y=l1;
        __nv_bfloat162 pl1; pl1.x=l2; pl1.y=l3;
        *reinterpret_cast<__nv_bfloat162*>(fh + c*4)     = ph0;
        *reinterpret_cast<__nv_bfloat162*>(fh + c*4 + 2) = ph1;
        *reinterpret_cast<__nv_bfloat162*>(fl + c*4)     = pl0;
        *reinterpret_cast<__nv_bfloat162*>(fl + c*4 + 2) = pl1;
    }

    #pragma unroll
    for (int sft = 16; sft > 0; sft >>= 1)
        chg2 += __shfl_xor_sync(0xFFFFFFFFu, chg2, sft);
    if ((tid & 31) == 0) red[tid >> 5] = chg2;
    __syncthreads();
    if (tid == 0) atomicAdd(&g_change, red[0] + red[1] + red[2] + red[3]);
}

__global__ void finish_kernel(float* __restrict__ out)
{
    out[0] = sqrtf(g_change);
}

// ---------------------------------------------------------------------------
extern "C" void kernel_launch(void* const* d_in, const int* in_sizes, int n_in,
                              void* d_out, int out_size)
{
    const float* text   = (const float*)d_in[0];
    const float* enc_w1 = (const float*)d_in[1];
    const float* enc_b1 = (const float*)d_in[2];
    const float* enc_w2 = (const float*)d_in[3];
    const float* enc_b2 = (const float*)d_in[4];
    const float* attr   = (const float*)d_in[5];
    const float* dec_w1 = (const float*)d_in[6];
    const float* dec_b1 = (const float*)d_in[7];
    const float* dec_w2 = (const float*)d_in[8];
    const float* dec_b2 = (const float*)d_in[9];

    float* out       = (float*)d_out;
    float* out_field = out;
    float* out_rec   = out + OUT_FIELD_ELEMS;
    float* out_chg   = out + OUT_FIELD_ELEMS + OUT_REC_ELEMS;

    bf16 *Thi, *Tlo, *Hhi, *Hlo, *Fhi, *Flo;
    bf16 *W1hi, *W1lo, *W2hi, *W2lo, *W3hi, *W3lo, *W4hi, *W4lo;
    float* EMB;
    cudaGetSymbolAddress((void**)&Thi,  g_Thi);  cudaGetSymbolAddress((void**)&Tlo,  g_Tlo);
    cudaGetSymbolAddress((void**)&Hhi,  g_Hhi);  cudaGetSymbolAddress((void**)&Hlo,  g_Hlo);
    cudaGetSymbolAddress((void**)&Fhi,  g_Fhi);  cudaGetSymbolAddress((void**)&Flo,  g_Flo);
    cudaGetSymbolAddress((void**)&W1hi, g_W1hi); cudaGetSymbolAddress((void**)&W1lo, g_W1lo);
    cudaGetSymbolAddress((void**)&W2hi, g_W2hi); cudaGetSymbolAddress((void**)&W2lo, g_W2lo);
    cudaGetSymbolAddress((void**)&W3hi, g_W3hi); cudaGetSymbolAddress((void**)&W3lo, g_W3lo);
    cudaGetSymbolAddress((void**)&W4hi, g_W4hi); cudaGetSymbolAddress((void**)&W4lo, g_W4lo);
    cudaGetSymbolAddress((void**)&EMB,  g_EMB);

    // Fused prep (text+weights split, Gram, reset) — one launch
    prep_kernel<<<16897, 256>>>(text, enc_w1, enc_w2, dec_w1, dec_w2, attr);

    // enc1: [M,100p128] @ W1 -> relu -> H (bf16 split), N=256
    mma_gemm<true, true><<<dim3(M_TOK / 128, 4), 256>>>(
        Thi, Tlo, 128, W1hi, W1lo, 128, enc_b1,
        nullptr, Hhi, Hlo, 256, 256, 2);
    // enc2: [M,256] @ W2 -> EMB fp32, N=128
    mma_gemm<false, false><<<dim3(M_TOK / 128, 2), 256>>>(
        Hhi, Hlo, 256, W2hi, W2lo, 256, enc_b2,
        EMB, nullptr, nullptr, 128, 128, 4);

    attractor_kernel<<<M_TOK / 128, 128>>>(EMB, attr, out_field);

    // dec1: [M,128] @ W3 -> relu -> H (bf16 split), N=256
    mma_gemm<true, true><<<dim3(M_TOK / 128, 4), 256>>>(
        Fhi, Flo, 128, W3hi, W3lo, 128, dec_b1,
        nullptr, Hhi, Hlo, 256, 256, 2);
    // dec2: [M,256] @ W4 -> out_rec fp32, N=100 (ldc=100)
    mma_gemm<false, false><<<dim3(M_TOK / 128, 2), 256>>>(
        Hhi, Hlo, 256, W4hi, W4lo, 256, dec_b2,
        out_rec, nullptr, nullptr, 100, 100, 4);

    finish_kernel<<<1, 1>>>(out_chg);
}